// round 4
// baseline (speedup 1.0000x reference)
#include <cuda_runtime.h>
#include <cstdint>

// CRF log-likelihood, B=128, L=1024, T=128.
// R4: 256 threads/CTA, split-K matvec. Thread (h=tid>>7, col=tid&127) owns
// rows [64h,64h+64) of exp(trans) column col in registers (f32x2 packed).
// 2 warps/SMSP hide LDS/FMA latency. Per step: partial matvec -> BAR ->
// combiner half (tid<128) finishes alpha while loader half (tid>=128) runs
// cp.async staging + pre-exponentiates emissions -> BAR.
// Exact pow-2 renormalization every 4 steps (integer exponent bookkeeping).

#define BB 128
#define LL 1024
#define TT 128

__device__ __forceinline__ void ffma2(unsigned long long &acc,
                                      unsigned long long a,
                                      unsigned long long b) {
    asm("fma.rn.f32x2 %0, %1, %2, %0;" : "+l"(acc) : "l"(a), "l"(b));
}
__device__ __forceinline__ unsigned long long add2(unsigned long long a,
                                                   unsigned long long b) {
    unsigned long long r;
    asm("add.rn.f32x2 %0, %1, %2;" : "=l"(r) : "l"(a), "l"(b));
    return r;
}
__device__ __forceinline__ float sum2(unsigned long long a) {
    return __uint_as_float((unsigned)(a & 0xffffffffull)) +
           __uint_as_float((unsigned)(a >> 32));
}
__device__ __forceinline__ void cp16(float *smem_ptr, const float *gptr) {
    unsigned s = (unsigned)__cvta_generic_to_shared(smem_ptr);
    asm volatile("cp.async.ca.shared.global [%0], [%1], 16;" :: "r"(s), "l"(gptr));
}

__global__ void zero_kernel(float *out) { out[0] = 0.f; }

__global__ __launch_bounds__(256, 1) void crf_kernel(
    const float *__restrict__ inputs,       // [B, L, T]
    const void *__restrict__ tags_raw,      // [B, L] int32 OR int64
    const float *__restrict__ trans,        // [T, T]
    const float *__restrict__ start_t,      // [T]
    const float *__restrict__ end_t,        // [T]
    float *__restrict__ out)                // [1]
{
    const int b = blockIdx.x;
    const int tid = threadIdx.x;
    const int lane = tid & 31;
    const int wid = tid >> 5;
    const int col = tid & 127;
    const int h = tid >> 7;                 // K-half

    __shared__ __align__(16) float u_sh[TT];        // combined alpha (linear)
    __shared__ __align__(16) float part[TT][2];     // split-K partials
    __shared__ __align__(16) unsigned red_u[4];
    __shared__ float red_f[8];
    __shared__ float s_num;
    __shared__ int is64_sh;
    __shared__ __align__(16) float ebuf[4][8][TT];  // 16 KB ring, holds EXP'd emissions

    const float *emitB = inputs + (size_t)b * (LL * TT);

    // ---------------- tags dtype detection ---------------------------------
    // int64 tags in [0,128): every odd int32 word is zero. int32 random tags:
    // 128 consecutive odd words all zero has prob ~0.
    if (tid == 0) {
        const int *p = (const int *)tags_raw;
        int any = 0;
        for (int i = 1; i < 257; i += 2) any |= p[i];
        is64_sh = (any == 0) ? 1 : 0;
    }
    __syncthreads();
    const int is64 = is64_sh;
    const int *t32 = (const int *)tags_raw;
    const long long *t64 = (const long long *)tags_raw;
    const long tagbase = (long)b * LL;
    auto get_tag = [&](int t) -> int {
        return is64 ? (int)t64[tagbase + t] : t32[tagbase + t];
    };

    // ---------------- numerator --------------------------------------------
    float np = 0.f;
    for (int t = tid; t < LL; t += 256) {
        int tag = get_tag(t);
        np += emitB[t * TT + tag];
        if (t < LL - 1) np += trans[tag * TT + get_tag(t + 1)];
    }
#pragma unroll
    for (int o = 16; o; o >>= 1) np += __shfl_xor_sync(0xffffffffu, np, o);
    if (lane == 0) red_f[wid] = np;
    __syncthreads();
    if (tid == 0) {
        float acc = 0.f;
        for (int w = 0; w < 8; w++) acc += red_f[w];
        s_num = acc + start_t[get_tag(0)] + end_t[get_tag(LL - 1)];
    }
    __syncthreads();

    // ---------------- E half-column into registers (f32x2 packed) ----------
    // Ec[p] = (E[64h+2p][col], E[64h+2p+1][col])
    unsigned long long Ec[32];
#pragma unroll
    for (int p = 0; p < 32; p++) {
        float lo = __expf(trans[(64 * h + 2 * p) * TT + col]);
        float hi = __expf(trans[(64 * h + 2 * p + 1) * TT + col]);
        Ec[p] = (unsigned long long)__float_as_uint(lo) |
                ((unsigned long long)__float_as_uint(hi) << 32);
    }

    // ---------------- init: alpha0, exact max normalize --------------------
    float un = 0.f;
    float mx0 = 0.f;
    if (h == 0) {
        float a0 = start_t[col] + emitB[col];
        float mv = a0;
#pragma unroll
        for (int o = 16; o; o >>= 1)
            mv = fmaxf(mv, __shfl_xor_sync(0xffffffffu, mv, o));
        if (lane == 0) red_f[wid] = mv;
    }
    __syncthreads();
    if (h == 0) {
        mx0 = fmaxf(fmaxf(red_f[0], red_f[1]), fmaxf(red_f[2], red_f[3]));
        float a0 = start_t[col] + emitB[col];
        un = __expf(a0 - mx0);            // u_0, max == 1
        u_sh[col] = un;
        unsigned wm = __reduce_max_sync(0xffffffffu, __float_as_uint(un));
        if (lane == 0) red_u[wid] = wm;
    }

    // ---------------- emission staging (loader half only) ------------------
    // Chunk c = emission rows [1+8c, 8+8c]; loader thread li copies bytes
    // [32*li, 32*li+32) of the flat 4 KB chunk into ring slot c&3, and later
    // exponentiates exactly its own 32 B (same-thread cp.async visibility).
    const long FLIM = (long)LL * TT;
    const int li = tid - 128;
    auto issue_chunk = [&](int c) {
        long base = (long)(1 + 8 * c) * TT + li * 8;
        long b0 = base;     if (b0 > FLIM - 8) b0 = FLIM - 8;
        long b1 = base + 4; if (b1 > FLIM - 4) b1 = FLIM - 4;
        float *dst = &ebuf[c & 3][0][0] + li * 8;
        cp16(dst, emitB + b0);
        cp16(dst + 4, emitB + b1);
        asm volatile("cp.async.commit_group;");
    };
    auto convert_own = [&](int c) {       // exp in place over own 8 floats
        float4 *q = (float4 *)(&ebuf[c & 3][0][0] + li * 8);
        float4 v0 = q[0], v1 = q[1];
        v0.x = __expf(v0.x); v0.y = __expf(v0.y);
        v0.z = __expf(v0.z); v0.w = __expf(v0.w);
        v1.x = __expf(v1.x); v1.y = __expf(v1.y);
        v1.z = __expf(v1.z); v1.w = __expf(v1.w);
        q[0] = v0; q[1] = v1;
    };
    if (h == 1) {
        issue_chunk(0);
        issue_chunk(1);
        asm volatile("cp.async.wait_group 0;");
        convert_own(0);                   // chunk 1 converted at step s=7
    }
    __syncthreads();

    // ---------------- forward recursion ------------------------------------
    // Step s = 0..1022 computes alpha_{s+1} (uses chunk s>>3, row s&7).
    // Renormalize: REDUX max at s%4==3 (and init), apply 2^-k at s%4==0.
    int ksum = 0;

    auto step_body = [&](int s, int ric) {
        // phase 1: split-K partial matvec over own 64 rows
        unsigned long long c0 = 0, c1 = 0, c2 = 0, c3 = 0;
        const ulonglong2 *uu =
            reinterpret_cast<const ulonglong2 *>(u_sh + 64 * h);
#pragma unroll
        for (int q = 0; q < 16; q++) {
            ulonglong2 U = uu[q];
            if (q & 1) { ffma2(c2, U.x, Ec[2 * q]); ffma2(c3, U.y, Ec[2 * q + 1]); }
            else       { ffma2(c0, U.x, Ec[2 * q]); ffma2(c1, U.y, Ec[2 * q + 1]); }
        }
        part[col][h] = sum2(add2(add2(c0, c1), add2(c2, c3)));
        __syncthreads();                  // BAR1: partials published

        if (h == 0) {
            // phase 2a: combine + emission + renorm -> new alpha
            float2 pp = *(const float2 *)part[col];
            float m = ebuf[(s >> 3) & 3][ric][col];   // pre-exponentiated
            float v = (pp.x + pp.y) * m;
            if ((s & 3) == 0) {           // apply pow-2 scale from last max
                uint4 r4 = *(const uint4 *)red_u;
                unsigned mb = max(max(r4.x, r4.y), max(r4.z, r4.w));
                int k = (int)(mb >> 23) - 127;
                ksum += k;
                v *= __uint_as_float((unsigned)(127 - k) << 23);
            }
            un = v;
            u_sh[col] = v;
            if ((s & 3) == 3) {
                unsigned w = __reduce_max_sync(0xffffffffu, __float_as_uint(v));
                if (lane == 0) red_u[wid] = w;
            }
        } else if (ric == 7) {
            // phase 2b: staging for chunk s>>3 + 2, convert chunk s>>3 + 1
            int c = s >> 3;
            if (c + 2 < 128) issue_chunk(c + 2);
            else asm volatile("cp.async.commit_group;");
            asm volatile("cp.async.wait_group 1;");
            convert_own(c + 1);
        }
        __syncthreads();                  // BAR2: alpha + conversions visible
    };

#pragma unroll 1
    for (int blk = 0; blk < 127; ++blk) {
#pragma unroll
        for (int sub = 0; sub < 8; ++sub)
            step_body(blk * 8 + sub, sub);
    }
#pragma unroll
    for (int sub = 0; sub < 7; ++sub)     // tail: s = 1016..1022
        step_body(1016 + sub, sub);

    // ---------------- denominator and output -------------------------------
    if (h == 0) {
        float contrib = un * __expf(end_t[col]);
#pragma unroll
        for (int o = 16; o; o >>= 1)
            contrib += __shfl_xor_sync(0xffffffffu, contrib, o);
        if (lane == 0) red_f[wid] = contrib;
    }
    __syncthreads();
    if (tid == 0) {
        float S = red_f[0] + red_f[1] + red_f[2] + red_f[3];
        double denom = (double)mx0 + (double)ksum * 0.69314718055994530942 +
                       (double)logf(S);
        atomicAdd(out, (float)((double)s_num - denom));
    }
}

extern "C" void kernel_launch(void *const *d_in, const int *in_sizes, int n_in,
                              void *d_out, int out_size) {
    const float *inputs    = (const float *)d_in[0];
    const void  *tags      = (const void *)d_in[1];
    // d_in[2] = mask (all ones by construction) — unused
    const float *trans     = (const float *)d_in[3];
    const float *start_t   = (const float *)d_in[4];
    const float *end_t     = (const float *)d_in[5];
    float *out = (float *)d_out;

    zero_kernel<<<1, 1>>>(out);
    crf_kernel<<<BB, 256>>>(inputs, tags, trans, start_t, end_t, out);
}

// round 5
// speedup vs baseline: 1.1197x; 1.1197x over previous
#include <cuda_runtime.h>
#include <cstdint>

// CRF log-likelihood, B=128, L=1024, T=128.
// R5: 256 threads/CTA, split-K with SAME-WARP halves.
//   col = wid*16 + (lane&15), h = lane>>4. Thread owns rows [64h,64h+64) of
//   exp(trans) column col in registers (f32x2 packed). Partial combine is a
//   single shfl_xor(16); both halves redundantly finish the epilogue -> no
//   serial tail, ONE barrier per step (double-buffered alpha).
// Emissions: per-thread register ring, LDG prefetched 8 steps ahead, __expf
// inline. Exact pow-2 renormalization every 4 steps (integer exponent sum).
// u halves padded 16B apart-of-phase in smem to kill LDS.128 bank conflicts.

#define BB 128
#define LL 1024
#define TT 128
#define UPAD 68   // floats per half-slot (64 + 4 pad) -> bases 272B apart

__device__ __forceinline__ void ffma2(unsigned long long &acc,
                                      unsigned long long a,
                                      unsigned long long b) {
    asm("fma.rn.f32x2 %0, %1, %2, %0;" : "+l"(acc) : "l"(a), "l"(b));
}
__device__ __forceinline__ unsigned long long add2(unsigned long long a,
                                                   unsigned long long b) {
    unsigned long long r;
    asm("add.rn.f32x2 %0, %1, %2;" : "=l"(r) : "l"(a), "l"(b));
    return r;
}
__device__ __forceinline__ float sum2(unsigned long long a) {
    return __uint_as_float((unsigned)(a & 0xffffffffull)) +
           __uint_as_float((unsigned)(a >> 32));
}

__global__ void zero_kernel(float *out) { out[0] = 0.f; }

__global__ __launch_bounds__(256, 1) void crf_kernel(
    const float *__restrict__ inputs,       // [B, L, T]
    const void *__restrict__ tags_raw,      // [B, L] int32 OR int64
    const float *__restrict__ trans,        // [T, T]
    const float *__restrict__ start_t,      // [T]
    const float *__restrict__ end_t,        // [T]
    float *__restrict__ out)                // [1]
{
    const int b = blockIdx.x;
    const int tid = threadIdx.x;
    const int lane = tid & 31;
    const int wid = tid >> 5;
    const int col = wid * 16 + (lane & 15);
    const int h = lane >> 4;                // K-half
    const int hbase = h * UPAD;
    const int wcol = col + ((col >> 6) << 2);   // padded store index

    __shared__ __align__(16) float u_sh[2][2 * UPAD];   // double-buffered alpha
    __shared__ __align__(16) unsigned red_u[8];
    __shared__ float red_f[8];
    __shared__ float s_num;
    __shared__ int is64_sh;

    const float *emitB = inputs + (size_t)b * (LL * TT);

    // ---------------- tags dtype detection ---------------------------------
    // int64 tags in [0,128): every odd int32 word is zero. int32 random tags:
    // 128 consecutive odd words all zero has prob ~0.
    if (tid == 0) {
        const int *p = (const int *)tags_raw;
        int any = 0;
        for (int i = 1; i < 257; i += 2) any |= p[i];
        is64_sh = (any == 0) ? 1 : 0;
    }
    __syncthreads();
    const int is64 = is64_sh;
    const int *t32 = (const int *)tags_raw;
    const long long *t64 = (const long long *)tags_raw;
    const long tagbase = (long)b * LL;
    auto get_tag = [&](int t) -> int {
        return is64 ? (int)t64[tagbase + t] : t32[tagbase + t];
    };

    // ---------------- numerator --------------------------------------------
    float np = 0.f;
    for (int t = tid; t < LL; t += 256) {
        int tag = get_tag(t);
        np += emitB[t * TT + tag];
        if (t < LL - 1) np += trans[tag * TT + get_tag(t + 1)];
    }
#pragma unroll
    for (int o = 16; o; o >>= 1) np += __shfl_xor_sync(0xffffffffu, np, o);
    if (lane == 0) red_f[wid] = np;
    __syncthreads();
    if (tid == 0) {
        float acc = 0.f;
        for (int w = 0; w < 8; w++) acc += red_f[w];
        s_num = acc + start_t[get_tag(0)] + end_t[get_tag(LL - 1)];
    }
    __syncthreads();

    // ---------------- E half-column into registers (f32x2 packed) ----------
    // Ec[p] = (E[64h+2p][col], E[64h+2p+1][col])
    unsigned long long Ec[32];
#pragma unroll
    for (int p = 0; p < 32; p++) {
        float lo = __expf(trans[(64 * h + 2 * p) * TT + col]);
        float hi = __expf(trans[(64 * h + 2 * p + 1) * TT + col]);
        Ec[p] = (unsigned long long)__float_as_uint(lo) |
                ((unsigned long long)__float_as_uint(hi) << 32);
    }

    // ---------------- init: alpha0, exact max normalize --------------------
    float a0 = start_t[col] + emitB[col];
    float mv = a0;
#pragma unroll
    for (int o = 16; o; o >>= 1)
        mv = fmaxf(mv, __shfl_xor_sync(0xffffffffu, mv, o));
    if (lane == 0) red_f[wid] = mv;
    __syncthreads();
    float mx0 = red_f[0];
    for (int w = 1; w < 8; w++) mx0 = fmaxf(mx0, red_f[w]);
    float un = __expf(a0 - mx0);            // u_0, max == 1
    if (h == 0) u_sh[0][wcol] = un;
    {
        unsigned wm = __reduce_max_sync(0xffffffffu, __float_as_uint(un));
        if (lane == 0) red_u[wid] = wm;
    }

    // ---------------- emission register ring (8 ahead) ---------------------
    float em[8];
#pragma unroll
    for (int i = 0; i < 8; i++) em[i] = emitB[(1 + i) * TT + col];
    __syncthreads();

    // ---------------- forward recursion ------------------------------------
    // Step s = 0..1022 computes alpha_{s+1}; emission row s+1 is em[s&7].
    // Renormalize: REDUX max at s%4==3 (and init), apply 2^-k at s%4==0.
    int ksum = 0;

    auto step_body = [&](int s, int j) {
        float m = __expf(em[j]);
        int nrow = s + 9; if (nrow > LL - 1) nrow = LL - 1;
        const float enew = emitB[nrow * TT + col];   // prefetch 8 steps ahead
        if ((s & 3) == 0) {              // apply pow-2 scale from last max
            uint4 ra = *(const uint4 *)red_u;
            uint4 rb = *(const uint4 *)(red_u + 4);
            unsigned mb = max(max(max(ra.x, ra.y), max(ra.z, ra.w)),
                              max(max(rb.x, rb.y), max(rb.z, rb.w)));
            int k = (int)(mb >> 23) - 127;
            ksum += k;
            m *= __uint_as_float((unsigned)(127 - k) << 23);
        }
        // partial matvec over own 64 rows
        unsigned long long c0 = 0, c1 = 0, c2 = 0, c3 = 0;
        const ulonglong2 *uu =
            reinterpret_cast<const ulonglong2 *>(&u_sh[s & 1][hbase]);
#pragma unroll
        for (int q = 0; q < 16; q++) {
            ulonglong2 U = uu[q];
            if (q & 1) { ffma2(c2, U.x, Ec[2 * q]); ffma2(c3, U.y, Ec[2 * q + 1]); }
            else       { ffma2(c0, U.x, Ec[2 * q]); ffma2(c1, U.y, Ec[2 * q + 1]); }
        }
        float p = sum2(add2(add2(c0, c1), add2(c2, c3)));
        p += __shfl_xor_sync(0xffffffffu, p, 16);    // in-warp K-combine
        const float v = p * m;                        // both halves identical
        un = v;
        em[j] = enew;
        if (h == 0) u_sh[(s + 1) & 1][wcol] = v;
        if ((s & 3) == 3) {
            unsigned w = __reduce_max_sync(0xffffffffu, __float_as_uint(v));
            if (lane == 0) red_u[wid] = w;
        }
        __syncthreads();                 // alpha + red_u published
    };

#pragma unroll 1
    for (int blk = 0; blk < 127; ++blk) {
#pragma unroll
        for (int sub = 0; sub < 8; ++sub)
            step_body(blk * 8 + sub, sub);
    }
#pragma unroll
    for (int sub = 0; sub < 7; ++sub)     // tail: s = 1016..1022
        step_body(1016 + sub, sub);

    // ---------------- denominator and output -------------------------------
    float contrib = (h == 0) ? un * __expf(end_t[col]) : 0.f;
#pragma unroll
    for (int o = 16; o; o >>= 1)
        contrib += __shfl_xor_sync(0xffffffffu, contrib, o);
    if (lane == 0) red_f[wid] = contrib;
    __syncthreads();
    if (tid == 0) {
        float S = 0.f;
        for (int w = 0; w < 8; w++) S += red_f[w];
        double denom = (double)mx0 + (double)ksum * 0.69314718055994530942 +
                       (double)logf(S);
        atomicAdd(out, (float)((double)s_num - denom));
    }
}

extern "C" void kernel_launch(void *const *d_in, const int *in_sizes, int n_in,
                              void *d_out, int out_size) {
    const float *inputs    = (const float *)d_in[0];
    const void  *tags      = (const void *)d_in[1];
    // d_in[2] = mask (all ones by construction) — unused
    const float *trans     = (const float *)d_in[3];
    const float *start_t   = (const float *)d_in[4];
    const float *end_t     = (const float *)d_in[5];
    float *out = (float *)d_out;

    zero_kernel<<<1, 1>>>(out);
    crf_kernel<<<BB, 256>>>(inputs, tags, trans, start_t, end_t, out);
}

// round 6
// speedup vs baseline: 1.5254x; 1.3623x over previous
#include <cuda_runtime.h>
#include <cstdint>

// CRF log-likelihood, B=128, L=1024, T=128.
// R6: forward-backward split. Z_b = alpha_511 . beta_512 (EXACT identity).
//   256 CTAs: blockIdx<128 -> forward chain over rows 0..511 (511 steps),
//   else backward chain beta_t = E (m_t o beta_{t+1}) over rows 1023..512
//   (512 steps). __launch_bounds__(128,2) -> all 256 CTAs co-resident;
//   the two chains per SM hide each other's serial-latency stalls.
// Per-chain step = R3's proven body: thread owns an E column (fwd) / row
// (bwd) in f32x2-packed registers; one barrier/step; exact pow-2 renorm
// (fwd: capture s%4==3 / apply s%4==0; bwd: lag-2, apply s%4==1).
// Combine kernel: per-chain dot product + logs + atomicAdd.

#define BB 128
#define LL 1024
#define TT 128
#define HALF 512
#define LN2 0.69314718055994530942

__device__ float g_alpha[BB][TT];
__device__ float g_beta[BB][TT];
__device__ float g_mx0[BB];
__device__ int g_kf[BB];
__device__ int g_kb[BB];

__device__ __forceinline__ void ffma2(unsigned long long &acc,
                                      unsigned long long a,
                                      unsigned long long b) {
    asm("fma.rn.f32x2 %0, %1, %2, %0;" : "+l"(acc) : "l"(a), "l"(b));
}
__device__ __forceinline__ unsigned long long add2(unsigned long long a,
                                                   unsigned long long b) {
    unsigned long long r;
    asm("add.rn.f32x2 %0, %1, %2;" : "=l"(r) : "l"(a), "l"(b));
    return r;
}
__device__ __forceinline__ float sum2(unsigned long long a) {
    return __uint_as_float((unsigned)(a & 0xffffffffull)) +
           __uint_as_float((unsigned)(a >> 32));
}

__global__ void zero_kernel(float *out) { out[0] = 0.f; }

__global__ __launch_bounds__(128, 2) void crf_main(
    const float *__restrict__ inputs,       // [B, L, T]
    const void *__restrict__ tags_raw,      // [B, L] int32 OR int64
    const float *__restrict__ trans,        // [T, T]
    const float *__restrict__ start_t,      // [T]
    const float *__restrict__ end_t,        // [T]
    float *__restrict__ out)                // [1]
{
    const int tid = threadIdx.x;
    const int lane = tid & 31;
    const int wid = tid >> 5;

    __shared__ __align__(16) float u_sh[2][TT];
    __shared__ __align__(16) unsigned red_u[4];
    __shared__ float red_f[4];

    unsigned long long Ec[64];   // packed E column (fwd) / row (bwd)
    float em[4];                 // emission LDG register ring (4 ahead)
    int ksum = 0;

    if (blockIdx.x < BB) {
        // ================= FORWARD: a_0 .. a_511 =========================
        const int b = blockIdx.x;
        const float *emitB = inputs + (size_t)b * (LL * TT);

        // ---- numerator (tags dtype: int64 from JAX is int32 in memory) ----
        {
            const int *t32 = (const int *)tags_raw;
            int odd = t32[(size_t)b * 2 * LL + 2 * tid + 1]; // sample odd words
            int is64 = !__syncthreads_or(odd != 0);
            const long long *t64 = (const long long *)tags_raw;
            const long tb = (long)b * LL;
            int tg0[8], tg1[8];
#pragma unroll
            for (int k = 0; k < 8; k++) {
                int t = tid + 128 * k;
                tg0[k] = is64 ? (int)t64[tb + t] : t32[tb + t];
                int t1 = t + 1; if (t1 > LL - 1) t1 = LL - 1;
                tg1[k] = is64 ? (int)t64[tb + t1] : t32[tb + t1];
            }
            float np = 0.f;
#pragma unroll
            for (int k = 0; k < 8; k++) {
                int t = tid + 128 * k;
                np += emitB[t * TT + tg0[k]];
                if (t < LL - 1) np += trans[tg0[k] * TT + tg1[k]];
            }
#pragma unroll
            for (int o = 16; o; o >>= 1) np += __shfl_xor_sync(0xffffffffu, np, o);
            if (lane == 0) red_f[wid] = np;
            __syncthreads();
            if (tid == 0) {
                float acc = red_f[0] + red_f[1] + red_f[2] + red_f[3];
                int tgA = is64 ? (int)t64[tb] : t32[tb];
                int tgZ = is64 ? (int)t64[tb + LL - 1] : t32[tb + LL - 1];
                atomicAdd(out, acc + start_t[tgA] + end_t[tgZ]);
            }
        }

        // ---- E column: Ec[q] = (E[2q][tid], E[2q+1][tid]) ----------------
#pragma unroll
        for (int q = 0; q < 64; q++) {
            float lo = __expf(trans[(2 * q) * TT + tid]);
            float hi = __expf(trans[(2 * q + 1) * TT + tid]);
            Ec[q] = (unsigned long long)__float_as_uint(lo) |
                    ((unsigned long long)__float_as_uint(hi) << 32);
        }

        // ---- init a_0: exact max-normalize -------------------------------
        float a0 = start_t[tid] + emitB[tid];
        float mv = a0;
#pragma unroll
        for (int o = 16; o; o >>= 1)
            mv = fmaxf(mv, __shfl_xor_sync(0xffffffffu, mv, o));
        __syncthreads();                  // red_f reuse safe
        if (lane == 0) red_f[wid] = mv;
        __syncthreads();
        const float mx0 =
            fmaxf(fmaxf(red_f[0], red_f[1]), fmaxf(red_f[2], red_f[3]));
        float un = __expf(a0 - mx0);      // u_0, max == 1
        u_sh[0][tid] = un;
        {
            unsigned wm = __reduce_max_sync(0xffffffffu, __float_as_uint(un));
            if (lane == 0) red_u[wid] = wm;
        }
#pragma unroll
        for (int i = 0; i < 4; i++) em[i] = emitB[(1 + i) * TT + tid];
        __syncthreads();

        // ---- 511 recursion steps: s uses emission row s+1 ----------------
        auto fwd_step = [&](int s, int j) {
            float m = __expf(em[j]);
            int nrow = s + 5; if (nrow > HALF - 1) nrow = HALF - 1;
            const float enew = emitB[nrow * TT + tid];
            if ((s & 3) == 0) {           // apply pow-2 scale (exact)
                uint4 r4 = *(const uint4 *)red_u;
                unsigned mb = max(max(r4.x, r4.y), max(r4.z, r4.w));
                int k = (int)(mb >> 23) - 127;
                ksum += k;
                m *= __uint_as_float((unsigned)(127 - k) << 23);
            }
            unsigned long long c0 = 0, c1 = 0, c2 = 0, c3 = 0;
            const ulonglong2 *uu =
                reinterpret_cast<const ulonglong2 *>(u_sh[s & 1]);
#pragma unroll
            for (int q = 0; q < 32; q++) {
                ulonglong2 U = uu[q];
                if (q & 1) { ffma2(c2, U.x, Ec[2 * q]); ffma2(c3, U.y, Ec[2 * q + 1]); }
                else       { ffma2(c0, U.x, Ec[2 * q]); ffma2(c1, U.y, Ec[2 * q + 1]); }
            }
            un = sum2(add2(add2(c0, c1), add2(c2, c3))) * m;
            em[j] = enew;
            u_sh[(s + 1) & 1][tid] = un;
            if ((s & 3) == 3) {
                unsigned w = __reduce_max_sync(0xffffffffu, __float_as_uint(un));
                if (lane == 0) red_u[wid] = w;
            }
            __syncthreads();
        };
#pragma unroll 1
        for (int blk = 0; blk < 127; ++blk) {
#pragma unroll
            for (int sub = 0; sub < 4; ++sub)
                fwd_step(blk * 4 + sub, sub);
        }
        fwd_step(508, 0); fwd_step(509, 1); fwd_step(510, 2);

        g_alpha[b][tid] = un;
        if (tid == 0) { g_kf[b] = ksum; g_mx0[b] = mx0; }
    } else {
        // ================= BACKWARD: beta_1024 -> beta_512 ================
        const int b = blockIdx.x - BB;
        const float *emitB = inputs + (size_t)b * (LL * TT);

        // ---- E row: Ec[q] = (E[tid][2q], E[tid][2q+1]) -------------------
        const float2 *trow = (const float2 *)(trans + tid * TT);
#pragma unroll
        for (int q = 0; q < 64; q++) {
            float2 tv = trow[q];
            float lo = __expf(tv.x), hi = __expf(tv.y);
            Ec[q] = (unsigned long long)__float_as_uint(lo) |
                    ((unsigned long long)__float_as_uint(hi) << 32);
        }

        // ---- init beta = exp(end) ----------------------------------------
        float bo = __expf(end_t[tid]);
        {
            unsigned wm = __reduce_max_sync(0xffffffffu, __float_as_uint(bo));
            if (lane == 0) red_u[wid] = wm;
        }
#pragma unroll
        for (int i = 0; i < 4; i++) em[i] = emitB[(1023 - i) * TT + tid];
        __syncthreads();

        // ---- 512 steps: s uses emission row 1023-s -----------------------
        // renorm: capture max(bo) at s%4==3 (post-matvec), apply at s%4==1.
        auto bwd_step = [&](int s, int j) {
            float m = __expf(em[j]);
            int nrow = 1023 - s - 4; if (nrow < HALF) nrow = HALF;
            const float enew = emitB[nrow * TT + tid];
            float v = bo * m;
            if ((s & 3) == 1) {
                uint4 r4 = *(const uint4 *)red_u;
                unsigned mb = max(max(r4.x, r4.y), max(r4.z, r4.w));
                int k = (int)(mb >> 23) - 127;
                ksum += k;
                v *= __uint_as_float((unsigned)(127 - k) << 23);
            }
            u_sh[s & 1][tid] = v;
            em[j] = enew;
            __syncthreads();              // v published
            unsigned long long c0 = 0, c1 = 0, c2 = 0, c3 = 0;
            const ulonglong2 *vv =
                reinterpret_cast<const ulonglong2 *>(u_sh[s & 1]);
#pragma unroll
            for (int q = 0; q < 32; q++) {
                ulonglong2 V = vv[q];
                if (q & 1) { ffma2(c2, V.x, Ec[2 * q]); ffma2(c3, V.y, Ec[2 * q + 1]); }
                else       { ffma2(c0, V.x, Ec[2 * q]); ffma2(c1, V.y, Ec[2 * q + 1]); }
            }
            bo = sum2(add2(add2(c0, c1), add2(c2, c3)));
            if ((s & 3) == 3) {
                unsigned w = __reduce_max_sync(0xffffffffu, __float_as_uint(bo));
                if (lane == 0) red_u[wid] = w;
            }
        };
#pragma unroll 1
        for (int blk = 0; blk < 128; ++blk) {
#pragma unroll
            for (int sub = 0; sub < 4; ++sub)
                bwd_step(blk * 4 + sub, sub);
        }

        g_beta[b][tid] = bo;
        if (tid == 0) g_kb[b] = ksum;
    }
}

__global__ __launch_bounds__(128) void crf_combine(float *__restrict__ out) {
    const int b = blockIdx.x;
    const int tid = threadIdx.x;
    const int lane = tid & 31;
    const int wid = tid >> 5;
    __shared__ float rf[4];

    float p = g_alpha[b][tid] * g_beta[b][tid];
#pragma unroll
    for (int o = 16; o; o >>= 1) p += __shfl_xor_sync(0xffffffffu, p, o);
    if (lane == 0) rf[wid] = p;
    __syncthreads();
    if (tid == 0) {
        float S = rf[0] + rf[1] + rf[2] + rf[3];
        double logZ = (double)g_mx0[b] +
                      (double)(g_kf[b] + g_kb[b]) * LN2 + log((double)S);
        atomicAdd(out, (float)(-logZ));
    }
}

extern "C" void kernel_launch(void *const *d_in, const int *in_sizes, int n_in,
                              void *d_out, int out_size) {
    const float *inputs    = (const float *)d_in[0];
    const void  *tags      = (const void *)d_in[1];
    // d_in[2] = mask (all ones by construction) — unused
    const float *trans     = (const float *)d_in[3];
    const float *start_t   = (const float *)d_in[4];
    const float *end_t     = (const float *)d_in[5];
    float *out = (float *)d_out;

    zero_kernel<<<1, 1>>>(out);
    crf_main<<<2 * BB, 128>>>(inputs, tags, trans, start_t, end_t, out);
    crf_combine<<<BB, 128>>>(out);
}